// round 7
// baseline (speedup 1.0000x reference)
#include <cuda_runtime.h>
#include <cuda_bf16.h>
#include <math.h>
#include <stdint.h>

// Shapes: B=4, N=256, F=64, H=256, A=16, T=3
#define Bn 4
#define Nn 256
#define Fn 64
#define Hn 256
#define An 16
#define Tn 3
#define BN 1024
#define NC 1280

typedef unsigned long long u64;

// ---------------- scratch (device globals) -----------------------------------
__device__ float d_h   [BN*Hn];
__device__ float d_big [BN*NC];     // [hi+b1 | hj | gh+bhh]; reused as pre-MLP tmp
__device__ float d_agg0[BN*Hn];
__device__ float d_deg [BN];
__device__ float d_Wc  [Hn*3*Hn];   // msg_W2 @ gru_Wih  (cols: r|z|n, 256 each)
__device__ float d_bc  [3*Hn];      // msg_b2 @ gru_Wih
__device__ float d_Wcat[Hn*NC];     // [W1_i | W1_j | Whh]
__device__ float d_bcat[NC];

// ---------------- f32x2 helpers ----------------------------------------------
#define FMA2(acc, a, b) \
    asm("fma.rn.f32x2 %0, %1, %2, %0;" : "+l"(acc) : "l"(a), "l"(b))
#define PACKDUP(d, s) \
    asm("mov.b64 %0, {%1, %1};" : "=l"(d) : "f"(s))
#define UNPACK2(lo, hi, s) \
    asm("mov.b64 {%0, %1}, %2;" : "=f"(lo), "=f"(hi) : "l"(s))

__device__ __forceinline__ void cpa16(void* s, const void* g) {
    uint32_t sa = (uint32_t)__cvta_generic_to_shared(s);
    asm volatile("cp.async.ca.shared.global [%0], [%1], 16;" :: "r"(sa), "l"(g));
}

// ---------------- fp32 GEMM, 64x64 tile, 256 thr, FFMA2, double-buffered -----
// C = f(A@B + bias + rowS*colV). A: MxK row-major, B: KxN row-major.
// M,N multiples of 64; K multiple of 16.
__global__ void __launch_bounds__(256)
gemm64q(const float* __restrict__ A, const float* __restrict__ Bm,
        const float* __restrict__ bias, float* __restrict__ C,
        int M, int N, int K, int doRelu,
        const float* __restrict__ rowS, const float* __restrict__ colV)
{
    __shared__ __align__(16) float As[2][16][68];   // [buf][k][m]
    __shared__ __align__(16) float Bs[2][16][64];   // [buf][k][n]

    int tid = threadIdx.x;
    int l = tid & 31, w = tid >> 5;
    int wm = w >> 2, wn = w & 3;        // warp grid 2(m)x4(n): 32 rows x 16 cols
    int rg = l >> 2, cg = l & 3;        // thread: 4 rows x 4 cols
    int row0 = blockIdx.y * 64, col0 = blockIdx.x * 64;

    int ar = tid >> 2, ak = (tid & 3) << 2;          // A: 256 float4 (64 rows x 4 quads)
    int bk = tid >> 4, bn = (tid & 15) << 2;         // B: 256 float4 (16 k x 16 quads)

    const float* Ab = A + (size_t)row0 * K;
    const float* Bb = Bm + col0;

    u64 acc[4][2];                       // 4 rows x col-pairs {0,1},{2,3}
    #pragma unroll
    for (int i = 0; i < 4; i++) { acc[i][0] = 0ull; acc[i][1] = 0ull; }

    // prologue
    float4 a0 = *(const float4*)(Ab + (size_t)ar * K + ak);
    As[0][ak+0][ar] = a0.x; As[0][ak+1][ar] = a0.y; As[0][ak+2][ar] = a0.z; As[0][ak+3][ar] = a0.w;
    cpa16(&Bs[0][bk][bn], Bb + (size_t)bk * N + bn);
    asm volatile("cp.async.commit_group;");

    int nch = K >> 4;
    int mrow = wm * 32 + rg * 4, ncol = wn * 16 + cg * 4;
    for (int ch = 0; ch < nch; ch++) {
        asm volatile("cp.async.wait_group 0;");
        __syncthreads();
        int buf = ch & 1, nb = buf ^ 1;
        int kn = (ch + 1) << 4;

        if (ch + 1 < nch) {
            a0 = *(const float4*)(Ab + (size_t)ar * K + kn + ak);
            cpa16(&Bs[nb][bk][bn], Bb + (size_t)(kn + bk) * N + bn);
            asm volatile("cp.async.commit_group;");
        }

        #pragma unroll
        for (int k = 0; k < 16; k++) {
            float4 av = *(float4*)&As[buf][k][mrow];
            ulonglong2 bq = *(ulonglong2*)&Bs[buf][k][ncol];
            u64 ad0, ad1, ad2, ad3;
            PACKDUP(ad0, av.x); PACKDUP(ad1, av.y); PACKDUP(ad2, av.z); PACKDUP(ad3, av.w);
            FMA2(acc[0][0], ad0, bq.x); FMA2(acc[0][1], ad0, bq.y);
            FMA2(acc[1][0], ad1, bq.x); FMA2(acc[1][1], ad1, bq.y);
            FMA2(acc[2][0], ad2, bq.x); FMA2(acc[2][1], ad2, bq.y);
            FMA2(acc[3][0], ad3, bq.x); FMA2(acc[3][1], ad3, bq.y);
        }

        if (ch + 1 < nch) {
            As[nb][ak+0][ar] = a0.x; As[nb][ak+1][ar] = a0.y;
            As[nb][ak+2][ar] = a0.z; As[nb][ak+3][ar] = a0.w;
        }
    }

    // epilogue
    int c0 = col0 + ncol;
    float4 bias0 = {0,0,0,0}, cv0 = {0,0,0,0};
    if (bias) bias0 = *(const float4*)(bias + c0);
    if (rowS) cv0 = *(const float4*)(colV + c0);

    #pragma unroll
    for (int i = 0; i < 4; i++) {
        int r = row0 + mrow + i;
        float rs = rowS ? rowS[r] : 0.f;
        float4 v;
        UNPACK2(v.x, v.y, acc[i][0]);
        UNPACK2(v.z, v.w, acc[i][1]);
        v.x += bias0.x + rs * cv0.x; v.y += bias0.y + rs * cv0.y;
        v.z += bias0.z + rs * cv0.z; v.w += bias0.w + rs * cv0.w;
        if (doRelu) {
            v.x = fmaxf(v.x, 0.f); v.y = fmaxf(v.y, 0.f);
            v.z = fmaxf(v.z, 0.f); v.w = fmaxf(v.w, 0.f);
        }
        *(float4*)(C + (size_t)r * N + c0) = v;
    }
}

// ---------------- fused gi-GEMM + GRU ----------------------------------------
// Block: 32 rows x 64 h-cols, all 3 gate segments (r,z,n).
// gi_s[r][c] = (agg0 @ Wc)[r][s*256+c] + deg[r]*bc[s*256+c] + bih[s*256+c]
// gh from big cols 512..1279. Applies GRU, writes h in place.
__global__ void __launch_bounds__(256)
gigru(const float* __restrict__ A,          // agg0: BN x 256
      const float* __restrict__ Wcm,        // 256 x 768
      const float* __restrict__ bih, const float* __restrict__ bc,
      const float* __restrict__ deg, const float* __restrict__ big,
      float* __restrict__ h)
{
    __shared__ __align__(16) float As[2][16][36];    // 32 rows
    __shared__ __align__(16) float Bs[2][16][192];   // 3 segs x 64 cols

    int tid = threadIdx.x;
    int l = tid & 31, w = tid >> 5;
    int wm = w >> 2, wn = w & 3;        // 2(m)x4(n): 16 rows x 16 cols
    int rg = l >> 2, cg = l & 3;        // thread: 2 rows x 4 cols (x3 segs)
    int g = blockIdx.x;                 // h-group 0..3 (64 cols each)
    int row0 = blockIdx.y * 32;

    int ar = tid >> 3, ak = (tid & 7) << 1;          // A: 32 rows x 8 k-pairs (float2)
    int bk = tid >> 4, bn = (tid & 15) << 2;         // per-seg B: 16 x 16 quads

    const float* Ab = A + (size_t)row0 * Hn;
    const float* Bb = Wcm + g * 64;

    u64 acc[2][3][2];
    #pragma unroll
    for (int i = 0; i < 2; i++)
        #pragma unroll
        for (int s = 0; s < 3; s++) { acc[i][s][0] = 0ull; acc[i][s][1] = 0ull; }

    // prologue
    float2 a0 = *(const float2*)(Ab + (size_t)ar * Hn + ak);
    As[0][ak+0][ar] = a0.x; As[0][ak+1][ar] = a0.y;
    #pragma unroll
    for (int s = 0; s < 3; s++)
        cpa16(&Bs[0][bk][s*64+bn], Bb + (size_t)bk * 768 + s * 256 + bn);
    asm volatile("cp.async.commit_group;");

    int mrow = wm * 16 + rg * 2, ncol = wn * 16 + cg * 4;
    for (int ch = 0; ch < 16; ch++) {
        asm volatile("cp.async.wait_group 0;");
        __syncthreads();
        int buf = ch & 1, nb = buf ^ 1;
        int kn = (ch + 1) << 4;

        if (ch < 15) {
            a0 = *(const float2*)(Ab + (size_t)ar * Hn + kn + ak);
            #pragma unroll
            for (int s = 0; s < 3; s++)
                cpa16(&Bs[nb][bk][s*64+bn], Bb + (size_t)(kn + bk) * 768 + s * 256 + bn);
            asm volatile("cp.async.commit_group;");
        }

        #pragma unroll
        for (int k = 0; k < 16; k++) {
            float2 av = *(float2*)&As[buf][k][mrow];
            u64 ad0, ad1;
            PACKDUP(ad0, av.x); PACKDUP(ad1, av.y);
            #pragma unroll
            for (int s = 0; s < 3; s++) {
                ulonglong2 bq = *(ulonglong2*)&Bs[buf][k][s*64 + ncol];
                FMA2(acc[0][s][0], ad0, bq.x); FMA2(acc[0][s][1], ad0, bq.y);
                FMA2(acc[1][s][0], ad1, bq.x); FMA2(acc[1][s][1], ad1, bq.y);
            }
        }

        if (ch < 15) {
            As[nb][ak+0][ar] = a0.x; As[nb][ak+1][ar] = a0.y;
        }
    }

    // epilogue: GRU
    int c0 = g * 64 + ncol;                       // global h-col of first of 4
    float4 bR = *(const float4*)(bih + c0);
    float4 bZ = *(const float4*)(bih + 256 + c0);
    float4 bN4 = *(const float4*)(bih + 512 + c0);
    float4 cR = *(const float4*)(bc + c0);
    float4 cZ = *(const float4*)(bc + 256 + c0);
    float4 cN4 = *(const float4*)(bc + 512 + c0);

    #pragma unroll
    for (int i = 0; i < 2; i++) {
        int r = row0 + mrow + i;
        float dg = deg[r];
        float ir[4], iz[4], in4[4];
        UNPACK2(ir[0], ir[1], acc[i][0][0]);  UNPACK2(ir[2], ir[3], acc[i][0][1]);
        UNPACK2(iz[0], iz[1], acc[i][1][0]);  UNPACK2(iz[2], iz[3], acc[i][1][1]);
        UNPACK2(in4[0], in4[1], acc[i][2][0]); UNPACK2(in4[2], in4[3], acc[i][2][1]);
        ir[0] += bR.x + dg*cR.x; ir[1] += bR.y + dg*cR.y; ir[2] += bR.z + dg*cR.z; ir[3] += bR.w + dg*cR.w;
        iz[0] += bZ.x + dg*cZ.x; iz[1] += bZ.y + dg*cZ.y; iz[2] += bZ.z + dg*cZ.z; iz[3] += bZ.w + dg*cZ.w;
        in4[0] += bN4.x + dg*cN4.x; in4[1] += bN4.y + dg*cN4.y; in4[2] += bN4.z + dg*cN4.z; in4[3] += bN4.w + dg*cN4.w;

        const float* bigr = big + (size_t)r * NC + 512;
        float4 hr = *(const float4*)(bigr + c0);
        float4 hz = *(const float4*)(bigr + 256 + c0);
        float4 hn = *(const float4*)(bigr + 512 + c0);
        float4 hv = *(const float4*)(h + (size_t)r * Hn + c0);

        float rr, zz, nn;
        float4 ho;
        rr = 1.f/(1.f+__expf(-(ir[0]+hr.x))); zz = 1.f/(1.f+__expf(-(iz[0]+hz.x)));
        nn = tanhf(in4[0] + rr*hn.x);          ho.x = (1.f-zz)*nn + zz*hv.x;
        rr = 1.f/(1.f+__expf(-(ir[1]+hr.y))); zz = 1.f/(1.f+__expf(-(iz[1]+hz.y)));
        nn = tanhf(in4[1] + rr*hn.y);          ho.y = (1.f-zz)*nn + zz*hv.y;
        rr = 1.f/(1.f+__expf(-(ir[2]+hr.z))); zz = 1.f/(1.f+__expf(-(iz[2]+hz.z)));
        nn = tanhf(in4[2] + rr*hn.z);          ho.z = (1.f-zz)*nn + zz*hv.z;
        rr = 1.f/(1.f+__expf(-(ir[3]+hr.w))); zz = 1.f/(1.f+__expf(-(iz[3]+hz.w)));
        nn = tanhf(in4[3] + rr*hn.w);          ho.w = (1.f-zz)*nn + zz*hv.w;

        *(float4*)(h + (size_t)r * Hn + c0) = ho;
    }
}

// ---------------- weight repack: Wcat = [W1_i | W1_j | Whh], bcat ------------
__global__ void repack(const float* __restrict__ msgW1, const float* __restrict__ Whh,
                       const float* __restrict__ msgb1, const float* __restrict__ bhh,
                       float* __restrict__ Wcat, float* __restrict__ bcat)
{
    int idx = blockIdx.x * 256 + threadIdx.x;        // over Hn*NC
    int k = idx / NC, n = idx % NC;
    float v;
    if (n < 256)       v = msgW1[(size_t)k * Hn + n];
    else if (n < 512)  v = msgW1[(size_t)(256 + k) * Hn + (n - 256)];
    else               v = Whh[(size_t)k * 768 + (n - 512)];
    Wcat[idx] = v;
    if (idx < NC)
        bcat[idx] = idx < 256 ? msgb1[idx] : (idx < 512 ? 0.f : bhh[idx - 512]);
}

// ---------------- E-aggregation ----------------------------------------------
// agg0[b,i,h] = sum_j adj * relu(hi'[i,h] + hj[j,h]); hi' at big[:,0:256]
#define IT 8
__global__ void eagg(const float* __restrict__ big, const int* __restrict__ adj,
                     float* __restrict__ agg0, float* __restrict__ deg)
{
    int b  = blockIdx.y;
    int i0 = blockIdx.x * IT;
    int h  = threadIdx.x;

    __shared__ float adjf[Nn][IT];

    float hir[IT], acc[IT];
    #pragma unroll
    for (int t = 0; t < IT; t++) {
        adjf[h][t] = (float)adj[((size_t)(b * Nn + i0 + t)) * Nn + h];
        hir[t] = big[((size_t)(b * Nn + i0 + t)) * NC + h];
        acc[t] = 0.f;
    }
    __syncthreads();

    const float* hjb = big + (size_t)b * Nn * NC + 256;
    #pragma unroll 2
    for (int j = 0; j < Nn; j++) {
        float hjv = hjb[(size_t)j * NC + h];
        float4 a04 = *(float4*)&adjf[j][0];
        float4 a47 = *(float4*)&adjf[j][4];
        acc[0] += a04.x * fmaxf(hir[0] + hjv, 0.f);
        acc[1] += a04.y * fmaxf(hir[1] + hjv, 0.f);
        acc[2] += a04.z * fmaxf(hir[2] + hjv, 0.f);
        acc[3] += a04.w * fmaxf(hir[3] + hjv, 0.f);
        acc[4] += a47.x * fmaxf(hir[4] + hjv, 0.f);
        acc[5] += a47.y * fmaxf(hir[5] + hjv, 0.f);
        acc[6] += a47.z * fmaxf(hir[6] + hjv, 0.f);
        acc[7] += a47.w * fmaxf(hir[7] + hjv, 0.f);
    }

    #pragma unroll
    for (int t = 0; t < IT; t++)
        agg0[((size_t)(b * Nn + i0 + t)) * Hn + h] = acc[t];

    if (h < IT) {
        float s = 0.f;
        for (int j = 0; j < Nn; j++) s += adjf[j][h];
        deg[b * Nn + i0 + h] = s;
    }
}

// ---------------- bc = msg_b2 @ gru_Wih (one warp per output) ----------------
__global__ void bck(const float* __restrict__ b2, const float* __restrict__ Wih,
                    float* __restrict__ bc)
{
    int warp = (blockIdx.x * blockDim.x + threadIdx.x) >> 5;
    int lane = threadIdx.x & 31;
    float s = 0.f;
    for (int k = lane; k < Hn; k += 32)
        s += b2[k] * Wih[(size_t)k * 768 + warp];
    #pragma unroll
    for (int o = 16; o; o >>= 1) s += __shfl_xor_sync(0xffffffffu, s, o);
    if (lane == 0) bc[warp] = s;
}

// ---------------- readout ----------------------------------------------------
__global__ void readout(const float* __restrict__ h,
                        const float* __restrict__ W1, const float* __restrict__ b1,
                        const float* __restrict__ W2, const float* __restrict__ b2,
                        float* __restrict__ out)
{
    __shared__ float gsh[Bn][Hn];
    __shared__ float hsh[Bn][Hn];
    int t = threadIdx.x;
    for (int b = 0; b < Bn; b++) {
        float s = 0.f;
        for (int i = 0; i < Nn; i++) s += h[((size_t)(b * Nn + i)) * Hn + t];
        gsh[b][t] = s;
    }
    __syncthreads();
    for (int b = 0; b < Bn; b++) {
        float s = b1[t];
        for (int k = 0; k < Hn; k++) s += gsh[b][k] * W1[(size_t)k * Hn + t];
        hsh[b][t] = fmaxf(s, 0.f);
    }
    __syncthreads();
    if (t < Bn * An) {
        int b = t >> 4, a = t & 15;
        float s = b2[a];
        for (int k = 0; k < Hn; k++) s += hsh[b][k] * W2[(size_t)k * An + a];
        out[b * An + a] = s;
    }
}

// ---------------- host launch ------------------------------------------------
extern "C" void kernel_launch(void* const* d_in, const int* in_sizes, int n_in,
                              void* d_out, int out_size)
{
    const float* X       = (const float*)d_in[0];
    const int*   adj     = (const int*)  d_in[1];
    const float* pre_W1  = (const float*)d_in[2];
    const float* pre_b1  = (const float*)d_in[3];
    const float* pre_W2  = (const float*)d_in[4];
    const float* pre_b2  = (const float*)d_in[5];
    const float* msg_W1  = (const float*)d_in[6];
    const float* msg_b1  = (const float*)d_in[7];
    const float* msg_W2  = (const float*)d_in[8];
    const float* msg_b2  = (const float*)d_in[9];
    const float* gru_Wih = (const float*)d_in[10];
    const float* gru_Whh = (const float*)d_in[11];
    const float* gru_bih = (const float*)d_in[12];
    const float* gru_bhh = (const float*)d_in[13];
    const float* ro_W1   = (const float*)d_in[14];
    const float* ro_b1   = (const float*)d_in[15];
    const float* ro_W2   = (const float*)d_in[16];
    const float* ro_b2   = (const float*)d_in[17];

    float *h, *big, *agg0, *deg, *Wc, *bc, *Wcat, *bcat;
    cudaGetSymbolAddress((void**)&h,    d_h);
    cudaGetSymbolAddress((void**)&big,  d_big);
    cudaGetSymbolAddress((void**)&agg0, d_agg0);
    cudaGetSymbolAddress((void**)&deg,  d_deg);
    cudaGetSymbolAddress((void**)&Wc,   d_Wc);
    cudaGetSymbolAddress((void**)&bc,   d_bc);
    cudaGetSymbolAddress((void**)&Wcat, d_Wcat);
    cudaGetSymbolAddress((void**)&bcat, d_bcat);

    // one-time: repack + composed weight
    repack<<<Hn * NC / 256, 256>>>(msg_W1, gru_Whh, msg_b1, gru_bhh, Wcat, bcat);
    gemm64q<<<dim3(768/64, Hn/64), 256>>>(msg_W2, gru_Wih, nullptr, Wc, Hn, 768, Hn, 0, nullptr, nullptr);
    bck<<<96, 256>>>(msg_b2, gru_Wih, bc);

    // pre-MLP: h = relu(X@W1+b1) @ W2 + b2   (big reused as temp)
    gemm64q<<<dim3(Hn/64, BN/64), 256>>>(X, pre_W1, pre_b1, big, BN, Hn, Fn, 1, nullptr, nullptr);
    gemm64q<<<dim3(Hn/64, BN/64), 256>>>(big, pre_W2, pre_b2, h, BN, Hn, Hn, 0, nullptr, nullptr);

    for (int it = 0; it < Tn; it++) {
        // [hi+b1 | hj | gh+bhh] = h @ Wcat + bcat
        gemm64q<<<dim3(NC/64, BN/64), 256>>>(h, Wcat, bcat, big, BN, NC, Hn, 0, nullptr, nullptr);
        eagg<<<dim3(Nn/IT, Bn), 256>>>(big, adj, agg0, deg);
        // gi = agg0@Wc + deg*bc + bih, then GRU -> h (fused)
        gigru<<<dim3(4, BN/32), 256>>>(agg0, Wc, gru_bih, bc, deg, big, h);
    }

    readout<<<1, 256>>>(h, ro_W1, ro_b1, ro_W2, ro_b2, (float*)d_out);
}

// round 8
// speedup vs baseline: 1.1485x; 1.1485x over previous
#include <cuda_runtime.h>
#include <cuda_bf16.h>
#include <math.h>
#include <stdint.h>

// Shapes: B=4, N=256, F=64, H=256, A=16, T=3
#define Bn 4
#define Nn 256
#define Fn 64
#define Hn 256
#define An 16
#define Tn 3
#define BN 1024
#define NC 1280
#define STAGES 3

typedef unsigned long long u64;

// ---------------- scratch (device globals) -----------------------------------
// K-major (transposed) activations: T[k][m], ld = BN
__device__ float d_XT  [Fn*BN];      // X^T        [64][1024]
__device__ float d_tT  [Hn*BN];      // pre-hidden [256][1024]
__device__ float d_hT  [Hn*BN];      // h^T        [256][1024]
__device__ float d_aT  [Hn*BN];      // agg0^T     [256][1024]
__device__ float d_M2T [Hn*Hn];      // msg_W2^T   [256][256]
__device__ float d_big2[BN*512];     // [hi+b1 | hj] row-major
__device__ float d_ghT [768*BN];     // gh^T (+bhh)
__device__ float d_giT [768*BN];     // gi^T
__device__ float d_deg [BN];
__device__ float d_Wc  [Hn*768];     // msg_W2 @ gru_Wih (row-major B operand)
__device__ float d_bc  [768];        // msg_b2 @ gru_Wih
__device__ float d_Wcat[Hn*NC];      // [W1_i | W1_j | Whh] row-major
__device__ float d_bcat[NC];

// ---------------- f32x2 helpers ----------------------------------------------
#define FMA2(acc, a, b) \
    asm("fma.rn.f32x2 %0, %1, %2, %0;" : "+l"(acc) : "l"(a), "l"(b))
#define PACKDUP(d, s) \
    asm("mov.b64 %0, {%1, %1};" : "=l"(d) : "f"(s))
#define UNPACK2(lo, hi, s) \
    asm("mov.b64 {%0, %1}, %2;" : "=f"(lo), "=f"(hi) : "l"(s))

__device__ __forceinline__ void cpa16(void* s, const void* g) {
    uint32_t sa = (uint32_t)__cvta_generic_to_shared(s);
    asm volatile("cp.async.ca.shared.global [%0], [%1], 16;" :: "r"(sa), "l"(g));
}

// ---------------- pipelined fp32 GEMM ----------------------------------------
// C = f(A@B + bias + rowS*colV), A given TRANSPOSED: At[k][m] (ld = ldaT).
// B row-major K x N. Tile 64x64, 128 thr, FFMA2, 3-stage cp.async pipeline.
// Output: block cols < splitCol -> Crow[r][c] (ld ldC);
//         block cols >= splitCol -> CtrT[(c-splitCol)][r] (ld ldT).
// splitCol, M, N multiples of 64; K multiple of 16 (nch >= 2).
__global__ void __launch_bounds__(128)
gemmT(const float* __restrict__ At, int ldaT,
      const float* __restrict__ Bm, int N, int K,
      const float* __restrict__ bias,
      const float* __restrict__ rowS, const float* __restrict__ colV,
      float* __restrict__ Crow, int ldC, int splitCol,
      float* __restrict__ CtrT, int ldT, int doRelu)
{
    __shared__ __align__(16) float As[STAGES][16][68];
    __shared__ __align__(16) float Bs[STAGES][16][64];

    int tid = threadIdx.x;
    int l = tid & 31, w = tid >> 5;
    int wm = w >> 1, wn = w & 1;          // warp grid 2x2: 32 rows x 32 cols
    int rg = l >> 2, cg = l & 3;          // thread: 4 rows x (4+4) cols
    int row0 = blockIdx.y * 64, col0 = blockIdx.x * 64;

    int lk = tid >> 4, lseg = (tid & 15) << 2;   // loader: k row, 16B seg
    int lk2 = lk + 8;

    const float* Abase = At + row0 + lseg;
    const float* Bbase = Bm + col0 + lseg;

    u64 acc[4][4];
    #pragma unroll
    for (int i = 0; i < 4; i++)
        #pragma unroll
        for (int j = 0; j < 4; j++) acc[i][j] = 0ull;

    int nch = K >> 4;
    // prologue: issue chunks 0 and 1
    #pragma unroll
    for (int p = 0; p < 2; p++) {
        int kc = p << 4;
        cpa16(&As[p][lk ][lseg], Abase + (size_t)(kc + lk ) * ldaT);
        cpa16(&As[p][lk2][lseg], Abase + (size_t)(kc + lk2) * ldaT);
        cpa16(&Bs[p][lk ][lseg], Bbase + (size_t)(kc + lk ) * N);
        cpa16(&Bs[p][lk2][lseg], Bbase + (size_t)(kc + lk2) * N);
        asm volatile("cp.async.commit_group;");
    }

    int mrow = wm * 32 + rg * 4, nc0 = wn * 32 + cg * 4;
    int s = 0;
    for (int ch = 0; ch < nch; ch++) {
        if (ch < nch - 1) asm volatile("cp.async.wait_group 1;");
        else              asm volatile("cp.async.wait_group 0;");
        __syncthreads();

        if (ch + 2 < nch) {
            int s2 = s + 2; if (s2 >= STAGES) s2 -= STAGES;
            int kc = (ch + 2) << 4;
            cpa16(&As[s2][lk ][lseg], Abase + (size_t)(kc + lk ) * ldaT);
            cpa16(&As[s2][lk2][lseg], Abase + (size_t)(kc + lk2) * ldaT);
            cpa16(&Bs[s2][lk ][lseg], Bbase + (size_t)(kc + lk ) * N);
            cpa16(&Bs[s2][lk2][lseg], Bbase + (size_t)(kc + lk2) * N);
            asm volatile("cp.async.commit_group;");
        }

        #pragma unroll
        for (int k = 0; k < 16; k++) {
            float4 av = *(float4*)&As[s][k][mrow];
            ulonglong2 b0 = *(ulonglong2*)&Bs[s][k][nc0];
            ulonglong2 b1 = *(ulonglong2*)&Bs[s][k][nc0 + 16];
            u64 ad0, ad1, ad2, ad3;
            PACKDUP(ad0, av.x); PACKDUP(ad1, av.y); PACKDUP(ad2, av.z); PACKDUP(ad3, av.w);
            FMA2(acc[0][0], ad0, b0.x); FMA2(acc[0][1], ad0, b0.y);
            FMA2(acc[0][2], ad0, b1.x); FMA2(acc[0][3], ad0, b1.y);
            FMA2(acc[1][0], ad1, b0.x); FMA2(acc[1][1], ad1, b0.y);
            FMA2(acc[1][2], ad1, b1.x); FMA2(acc[1][3], ad1, b1.y);
            FMA2(acc[2][0], ad2, b0.x); FMA2(acc[2][1], ad2, b0.y);
            FMA2(acc[2][2], ad2, b1.x); FMA2(acc[2][3], ad2, b1.y);
            FMA2(acc[3][0], ad3, b0.x); FMA2(acc[3][1], ad3, b0.y);
            FMA2(acc[3][2], ad3, b1.x); FMA2(acc[3][3], ad3, b1.y);
        }
        s++; if (s >= STAGES) s = 0;
    }

    // epilogue
    float vv[4][8];
    #pragma unroll
    for (int i = 0; i < 4; i++) {
        UNPACK2(vv[i][0], vv[i][1], acc[i][0]);
        UNPACK2(vv[i][2], vv[i][3], acc[i][1]);
        UNPACK2(vv[i][4], vv[i][5], acc[i][2]);
        UNPACK2(vv[i][6], vv[i][7], acc[i][3]);
    }
    const int cofs[8] = {0, 1, 2, 3, 16, 17, 18, 19};
    int c0 = col0 + nc0;
    float bj[8], cvj[8];
    #pragma unroll
    for (int j = 0; j < 8; j++) {
        int c = c0 + cofs[j];
        bj[j]  = bias ? bias[c] : 0.f;
        cvj[j] = rowS ? colV[c] : 0.f;
    }
    #pragma unroll
    for (int i = 0; i < 4; i++) {
        int r = row0 + mrow + i;
        float rs = rowS ? rowS[r] : 0.f;
        #pragma unroll
        for (int j = 0; j < 8; j++) {
            float v = vv[i][j] + bj[j] + rs * cvj[j];
            if (doRelu) v = fmaxf(v, 0.f);
            vv[i][j] = v;
        }
    }
    if (col0 < splitCol) {
        #pragma unroll
        for (int i = 0; i < 4; i++) {
            int r = row0 + mrow + i;
            float4 o0 = {vv[i][0], vv[i][1], vv[i][2], vv[i][3]};
            float4 o1 = {vv[i][4], vv[i][5], vv[i][6], vv[i][7]};
            *(float4*)(Crow + (size_t)r * ldC + c0)      = o0;
            *(float4*)(Crow + (size_t)r * ldC + c0 + 16) = o1;
        }
    } else {
        int rbase = row0 + mrow;
        #pragma unroll
        for (int j = 0; j < 8; j++) {
            float4 o = {vv[0][j], vv[1][j], vv[2][j], vv[3][j]};
            *(float4*)(CtrT + (size_t)(c0 + cofs[j] - splitCol) * ldT + rbase) = o;
        }
    }
}

// ---------------- prep: transposes + Wcat/bcat -------------------------------
__global__ void prep(const float* __restrict__ X, const float* __restrict__ msgW2,
                     const float* __restrict__ msgW1, const float* __restrict__ Whh,
                     const float* __restrict__ msgb1, const float* __restrict__ bhh,
                     float* __restrict__ XT, float* __restrict__ M2T,
                     float* __restrict__ Wcat, float* __restrict__ bcat)
{
    int blk = blockIdx.x, t = threadIdx.x;
    if (blk < 256) {                     // XT[k][m] = X[m][k], 64x1024
        int i = blk * 256 + t;
        int k = i >> 10, m = i & 1023;
        XT[i] = X[(size_t)m * Fn + k];
    } else if (blk < 512) {              // M2T[k][m] = msg_W2[m][k], 256x256
        int i = (blk - 256) * 256 + t;
        int k = i >> 8, m = i & 255;
        M2T[i] = msgW2[(size_t)m * Hn + k];
    } else {                             // Wcat[k][n], 256x1280
        int i = (blk - 512) * 256 + t;
        int k = i / NC, n = i % NC;
        float v;
        if (n < 256)      v = msgW1[(size_t)k * Hn + n];
        else if (n < 512) v = msgW1[(size_t)(256 + k) * Hn + (n - 256)];
        else              v = Whh[(size_t)k * 768 + (n - 512)];
        Wcat[i] = v;
        if (i < NC)
            bcat[i] = i < 256 ? msgb1[i] : (i < 512 ? 0.f : bhh[i - 512]);
    }
}

// ---------------- E-aggregation ----------------------------------------------
// agg0T[h][row] = sum_j adj[row,j]*relu(hi'[row,h] + hj[j,h]); hi'|hj in big2
#define IT 8
__global__ void eagg(const float* __restrict__ big2, const int* __restrict__ adj,
                     float* __restrict__ aT, float* __restrict__ deg)
{
    int b  = blockIdx.y;
    int i0 = blockIdx.x * IT;
    int h  = threadIdx.x;

    __shared__ float adjf[Nn][IT];

    float hir[IT], acc[IT];
    #pragma unroll
    for (int t = 0; t < IT; t++) {
        adjf[h][t] = (float)adj[((size_t)(b * Nn + i0 + t)) * Nn + h];
        hir[t] = big2[((size_t)(b * Nn + i0 + t)) * 512 + h];
        acc[t] = 0.f;
    }
    __syncthreads();

    const float* hjb = big2 + (size_t)b * Nn * 512 + 256;
    #pragma unroll 2
    for (int j = 0; j < Nn; j++) {
        float hjv = hjb[(size_t)j * 512 + h];
        float4 a04 = *(float4*)&adjf[j][0];
        float4 a47 = *(float4*)&adjf[j][4];
        acc[0] += a04.x * fmaxf(hir[0] + hjv, 0.f);
        acc[1] += a04.y * fmaxf(hir[1] + hjv, 0.f);
        acc[2] += a04.z * fmaxf(hir[2] + hjv, 0.f);
        acc[3] += a04.w * fmaxf(hir[3] + hjv, 0.f);
        acc[4] += a47.x * fmaxf(hir[4] + hjv, 0.f);
        acc[5] += a47.y * fmaxf(hir[5] + hjv, 0.f);
        acc[6] += a47.z * fmaxf(hir[6] + hjv, 0.f);
        acc[7] += a47.w * fmaxf(hir[7] + hjv, 0.f);
    }

    #pragma unroll
    for (int t = 0; t < IT; t++)
        aT[(size_t)h * BN + b * Nn + i0 + t] = acc[t];

    if (h < IT) {
        float s = 0.f;
        for (int j = 0; j < Nn; j++) s += adjf[j][h];
        deg[b * Nn + i0 + h] = s;
    }
}

// ---------------- bc = msg_b2 @ gru_Wih (one warp per output) ----------------
__global__ void bck(const float* __restrict__ b2, const float* __restrict__ Wih,
                    float* __restrict__ bc)
{
    int warp = (blockIdx.x * blockDim.x + threadIdx.x) >> 5;
    int lane = threadIdx.x & 31;
    float s = 0.f;
    for (int k = lane; k < Hn; k += 32)
        s += b2[k] * Wih[(size_t)k * 768 + warp];
    #pragma unroll
    for (int o = 16; o; o >>= 1) s += __shfl_xor_sync(0xffffffffu, s, o);
    if (lane == 0) bc[warp] = s;
}

// ---------------- GRU elementwise (fully coalesced on transposed layouts) ----
__global__ void gru(const float* __restrict__ giT, const float* __restrict__ ghT,
                    float* __restrict__ hT)
{
    int id = blockIdx.x * 256 + threadIdx.x;   // over Hn*BN, m fastest
    int m = id & 1023, c = id >> 10;
    float ir = giT[(size_t)c * BN + m];
    float iz = giT[(size_t)(c + 256) * BN + m];
    float in = giT[(size_t)(c + 512) * BN + m];
    float hr = ghT[(size_t)c * BN + m];
    float hz = ghT[(size_t)(c + 256) * BN + m];
    float hn = ghT[(size_t)(c + 512) * BN + m];
    float r = 1.f / (1.f + __expf(-(ir + hr)));
    float z = 1.f / (1.f + __expf(-(iz + hz)));
    float n = tanhf(in + r * hn);
    hT[id] = (1.f - z) * n + z * hT[id];
}

// ---------------- readout (4 blocks, one per batch) --------------------------
__global__ void readout(const float* __restrict__ hT,
                        const float* __restrict__ W1, const float* __restrict__ b1,
                        const float* __restrict__ W2, const float* __restrict__ b2,
                        float* __restrict__ out)
{
    __shared__ float gsh[Hn];
    __shared__ float hsh[Hn];
    int b = blockIdx.x, t = threadIdx.x;

    float s = 0.f;
    const float* hrow = hT + (size_t)t * BN + b * Nn;
    #pragma unroll 4
    for (int i = 0; i < Nn; i++) s += hrow[i];
    gsh[t] = s;
    __syncthreads();

    float s2 = b1[t];
    for (int k = 0; k < Hn; k++) s2 += gsh[k] * W1[(size_t)k * Hn + t];
    hsh[t] = fmaxf(s2, 0.f);
    __syncthreads();

    if (t < An) {
        float s3 = b2[t];
        for (int k = 0; k < Hn; k++) s3 += hsh[k] * W2[(size_t)k * An + t];
        out[b * An + t] = s3;
    }
}

// ---------------- host launch ------------------------------------------------
extern "C" void kernel_launch(void* const* d_in, const int* in_sizes, int n_in,
                              void* d_out, int out_size)
{
    const float* X       = (const float*)d_in[0];
    const int*   adj     = (const int*)  d_in[1];
    const float* pre_W1  = (const float*)d_in[2];
    const float* pre_b1  = (const float*)d_in[3];
    const float* pre_W2  = (const float*)d_in[4];
    const float* pre_b2  = (const float*)d_in[5];
    const float* msg_W1  = (const float*)d_in[6];
    const float* msg_b1  = (const float*)d_in[7];
    const float* msg_W2  = (const float*)d_in[8];
    const float* msg_b2  = (const float*)d_in[9];
    const float* gru_Wih = (const float*)d_in[10];
    const float* gru_Whh = (const float*)d_in[11];
    const float* gru_bih = (const float*)d_in[12];
    const float* gru_bhh = (const float*)d_in[13];
    const float* ro_W1   = (const float*)d_in[14];
    const float* ro_b1   = (const float*)d_in[15];
    const float* ro_W2   = (const float*)d_in[16];
    const float* ro_b2   = (const float*)d_in[17];

    float *XT,*tT,*hT,*aT,*M2T,*big2,*ghT,*giT,*deg,*Wc,*bc,*Wcat,*bcat;
    cudaGetSymbolAddress((void**)&XT,  d_XT);
    cudaGetSymbolAddress((void**)&tT,  d_tT);
    cudaGetSymbolAddress((void**)&hT,  d_hT);
    cudaGetSymbolAddress((void**)&aT,  d_aT);
    cudaGetSymbolAddress((void**)&M2T, d_M2T);
    cudaGetSymbolAddress((void**)&big2,d_big2);
    cudaGetSymbolAddress((void**)&ghT, d_ghT);
    cudaGetSymbolAddress((void**)&giT, d_giT);
    cudaGetSymbolAddress((void**)&deg, d_deg);
    cudaGetSymbolAddress((void**)&Wc,  d_Wc);
    cudaGetSymbolAddress((void**)&bc,  d_bc);
    cudaGetSymbolAddress((void**)&Wcat,d_Wcat);
    cudaGetSymbolAddress((void**)&bcat,d_bcat);

    // prep: XT, M2T, Wcat, bcat; bc
    prep<<<512 + Hn * NC / 256, 256>>>(X, msg_W2, msg_W1, gru_Whh, msg_b1, gru_bhh,
                                       XT, M2T, Wcat, bcat);
    bck<<<96, 256>>>(msg_b2, gru_Wih, bc);

    // Wc = msg_W2 @ gru_Wih (row-major out; A = M2T)
    gemmT<<<dim3(12, 4), 128>>>(M2T, Hn, gru_Wih, 768, Hn,
                                nullptr, nullptr, nullptr,
                                Wc, 768, 768, nullptr, 0, 0);

    // pre-MLP: tT = relu(X@W1+b1)^T ; hT = (t@W2+b2)^T
    gemmT<<<dim3(4, 16), 128>>>(XT, BN, pre_W1, Hn, Fn,
                                pre_b1, nullptr, nullptr,
                                nullptr, 0, 0, tT, BN, 1);
    gemmT<<<dim3(4, 16), 128>>>(tT, BN, pre_W2, Hn, Hn,
                                pre_b2, nullptr, nullptr,
                                nullptr, 0, 0, hT, BN, 0);

    for (int it = 0; it < Tn; it++) {
        // [hi+b1 | hj] -> big2 (row-major), gh+bhh -> ghT (transposed)
        gemmT<<<dim3(20, 16), 128>>>(hT, BN, Wcat, NC, Hn,
                                     bcat, nullptr, nullptr,
                                     big2, 512, 512, ghT, BN, 0);
        eagg<<<dim3(Nn / IT, Bn), 256>>>(big2, adj, aT, deg);
        // giT = (agg0 @ Wc + deg*bc + bih)^T
        gemmT<<<dim3(12, 16), 128>>>(aT, BN, Wc, 768, Hn,
                                     gru_bih, deg, bc,
                                     nullptr, 0, 0, giT, BN, 0);
        gru<<<Hn * BN / 256, 256>>>(giT, ghT, hT);
    }

    readout<<<Bn, 256>>>(hT, ro_W1, ro_b1, ro_W2, ro_b2, (float*)d_out);
}